// round 9
// baseline (speedup 1.0000x reference)
#include <cuda_runtime.h>
#include <cuda_fp16.h>
#include <cstdint>
#include <math.h>

#define B_  4
#define S_  2048
#define H_  1024
#define NH_ 16
#define HD_ 64
#define L2E 1.44269504088896f

// f16 scratch.
__device__ __half g_hs[8192 * 1024];          // hidden, f16 [8192][1024]
__device__ __half g_wt[3][1024 * 1024];       // W^T f16 [n][k] for Q,K,V
__device__ __half g_qh[64 * 2048 * 64];       // Q f16 [bh][s][d], scaled log2e/8
__device__ __half g_kh[64 * 2048 * 64];       // K f16 [bh][s][d]
__device__ __half g_vt[64 * 64 * 2048];       // V^T f16 [bh][d][s]

__device__ __forceinline__ void mma16(float* c, const unsigned* a, const unsigned* b) {
    asm volatile(
        "mma.sync.aligned.m16n8k16.row.col.f32.f16.f16.f32 "
        "{%0,%1,%2,%3}, {%4,%5,%6,%7}, {%8,%9}, {%0,%1,%2,%3};\n"
        : "+f"(c[0]), "+f"(c[1]), "+f"(c[2]), "+f"(c[3])
        : "r"(a[0]), "r"(a[1]), "r"(a[2]), "r"(a[3]), "r"(b[0]), "r"(b[1]));
}

__device__ __forceinline__ void ldsm4(unsigned& r0, unsigned& r1,
                                      unsigned& r2, unsigned& r3, unsigned addr) {
    asm volatile("ldmatrix.sync.aligned.m8n8.x4.shared.b16 {%0,%1,%2,%3}, [%4];\n"
        : "=r"(r0), "=r"(r1), "=r"(r2), "=r"(r3) : "r"(addr));
}

__device__ __forceinline__ void cpa16(void* dst, const void* src) {
    unsigned d = (unsigned)__cvta_generic_to_shared(dst);
    asm volatile("cp.async.cg.shared.global [%0], [%1], 16;\n" :: "r"(d), "l"(src));
}
#define CP_COMMIT asm volatile("cp.async.commit_group;\n" ::: "memory")
#define CP_WAIT1  asm volatile("cp.async.wait_group 1;\n" ::: "memory")

__device__ __forceinline__ unsigned h2u(float x, float y) {
    __half2 h = __floats2half2_rn(x, y);
    return *reinterpret_cast<unsigned*>(&h);
}

// ---------------------------------------------------------------------------
// Prep 1: hidden f32 -> f16.
// ---------------------------------------------------------------------------
__global__ __launch_bounds__(256) void cvt_hs(const float* __restrict__ hs) {
    int i = blockIdx.x * 256 + threadIdx.x;
    float4 v = ((const float4*)hs)[i];
    ((uint2*)g_hs)[i] = make_uint2(h2u(v.x, v.y), h2u(v.z, v.w));
}

// ---------------------------------------------------------------------------
// Prep 2: W -> W^T f16 (tiled transpose). grid (32,32,3), block (32,8).
// ---------------------------------------------------------------------------
__global__ __launch_bounds__(256) void cvt_wt(
    const float* __restrict__ Wq, const float* __restrict__ Wk,
    const float* __restrict__ Wv)
{
    __shared__ float t[32][33];
    const float* W = blockIdx.z == 0 ? Wq : (blockIdx.z == 1 ? Wk : Wv);
    __half* wt = g_wt[blockIdx.z];
    int tx = threadIdx.x, ty = threadIdx.y;
    int n0 = blockIdx.x * 32, k0 = blockIdx.y * 32;
    #pragma unroll
    for (int j = 0; j < 4; j++)
        t[ty + 8 * j][tx] = W[(size_t)(k0 + ty + 8 * j) * H_ + n0 + tx];
    __syncthreads();
    #pragma unroll
    for (int j = 0; j < 4; j++)
        wt[(size_t)(n0 + ty + 8 * j) * H_ + k0 + tx] =
            __float2half(t[tx][ty + 8 * j]);
}

// ---------------------------------------------------------------------------
// Kernel 1: fused QKV projection. BM=128, BN=128, BK=64.
//   8 warps (4m x 2n), warp tile 32x64. ldmatrix.x4 fragment loads.
// ---------------------------------------------------------------------------
#define QTS 36   // row stride in words (32 data + 4 pad); 36%32=4 -> LDSM conflict-free
#define QKV_SMEM (4 * 128 * QTS * 4)   // A[2][128][QTS] + B[2][128][QTS]

__global__ __launch_bounds__(256, 2) void qkv_proj(
    const float* __restrict__ bq, const float* __restrict__ bk,
    const float* __restrict__ bv,
    const float* __restrict__ qe, const float* __restrict__ ke,
    const float* __restrict__ ve,
    const int* __restrict__ indexp)
{
    extern __shared__ unsigned qsm[];
    unsigned* AsW = qsm;                  // [2][128][QTS]
    unsigned* BsW = qsm + 2 * 128 * QTS;  // [2][128][QTS]
#define AT(bf,r,w) AsW[(bf)*128*QTS + (r)*QTS + (w)]
#define BT(bf,r,w) BsW[(bf)*128*QTS + (r)*QTS + (w)]

    const int tid  = threadIdx.x;
    const int lane = tid & 31;
    const int wid  = tid >> 5;
    const int g    = lane >> 2;
    const int t    = lane & 3;
    const int wm   = wid & 3;
    const int wn   = wid >> 2;
    const int grp  = lane >> 3;   // ldmatrix tile group
    const int lr   = lane & 7;    // row within tile

    const int nb  = blockIdx.x;   // 0..23, 8 per matrix
    const int mb  = blockIdx.y;   // 0..63
    const int sel = nb >> 3;

    const __half* wt  = g_wt[sel];
    const float* bias = sel == 0 ? bq : (sel == 1 ? bk : bv);
    const float* emb  = (sel == 0 ? qe : (sel == 1 ? ke : ve)) + indexp[0] * H_;
    const float sc    = sel == 0 ? (0.125f * L2E) : 1.0f;

    const int colm = (nb & 7) * 128;
    const int row0 = mb * 128;

    // per-lane ldmatrix base addresses (shared-space)
    const unsigned aBase = (unsigned)__cvta_generic_to_shared(AsW)
        + ((wm * 32 + (grp & 1) * 8 + lr) * QTS + (grp >> 1) * 4) * 4;
    const unsigned bBase = (unsigned)__cvta_generic_to_shared(BsW)
        + ((wn * 64 + (grp >> 1) * 8 + lr) * QTS + (grp & 1) * 4) * 4;

    float acc[2][8][4] = {};

    auto stage = [&](int kt, int bf) {
        #pragma unroll
        for (int i = 0; i < 4; i++) {
            int idx = tid + i * 256;
            int r = idx >> 3, ch = idx & 7;
            cpa16(&AT(bf, r, ch * 4), &g_hs[(size_t)(row0 + r) * H_ + kt + ch * 8]);
            cpa16(&BT(bf, r, ch * 4), &wt[(size_t)(colm + r) * H_ + kt + ch * 8]);
        }
    };

    stage(0, 0);
    CP_COMMIT;

    for (int it = 0; it < H_ / 64; it++) {
        const int bf = it & 1;
        if (it + 1 < H_ / 64) stage((it + 1) * 64, bf ^ 1);
        CP_COMMIT;
        CP_WAIT1;
        __syncthreads();

        const unsigned ab = aBase + bf * (128 * QTS * 4);
        const unsigned bb = bBase + bf * (128 * QTS * 4);
        #pragma unroll
        for (int kk = 0; kk < 4; kk++) {     // 4 k16 steps
            unsigned a0[4], a1[4];
            ldsm4(a0[0], a0[1], a0[2], a0[3], ab + (kk * 8) * 4);
            ldsm4(a1[0], a1[1], a1[2], a1[3], ab + (16 * QTS + kk * 8) * 4);
            #pragma unroll
            for (int j = 0; j < 4; j++) {    // nt pairs
                unsigned r0, r1, r2, r3;
                ldsm4(r0, r1, r2, r3, bb + (j * 16 * QTS + kk * 8) * 4);
                unsigned f0[2] = { r0, r1 }, f1[2] = { r2, r3 };
                mma16(acc[0][2 * j],     a0, f0);
                mma16(acc[1][2 * j],     a1, f0);
                mma16(acc[0][2 * j + 1], a0, f1);
                mma16(acc[1][2 * j + 1], a1, f1);
            }
        }
        __syncthreads();
    }

    // Epilogue: +bias+emb, (Q: *log2e/8), f16, scatter.
    #pragma unroll
    for (int nt = 0; nt < 8; nt++) {
        const int cm   = colm + wn * 64 + nt * 8 + 2 * t;
        const float b0 = bias[cm]     + emb[cm];
        const float b1 = bias[cm + 1] + emb[cm + 1];
        const int head = cm >> 6;
        const int d    = cm & 63;
        #pragma unroll
        for (int mt = 0; mt < 2; mt++) {
            int row = row0 + wm * 32 + mt * 16 + g;
            int bt  = row >> 11;
            int s   = row & 2047;
            int bh  = bt * NH_ + head;
            float x0 = (acc[mt][nt][0] + b0) * sc;
            float x1 = (acc[mt][nt][1] + b1) * sc;
            float x2 = (acc[mt][nt][2] + b0) * sc;
            float x3 = (acc[mt][nt][3] + b1) * sc;
            if (sel < 2) {
                __half* dst = (sel ? g_kh : g_qh)
                            + ((size_t)bh * S_ + s) * HD_ + d;
                *(unsigned*)dst             = h2u(x0, x1);
                *(unsigned*)(dst + 8 * HD_) = h2u(x2, x3);
            } else {
                __half* dst = g_vt + (size_t)bh * HD_ * S_;
                dst[(size_t)d       * S_ + s]     = __float2half(x0);
                dst[(size_t)(d + 1) * S_ + s]     = __float2half(x1);
                dst[(size_t)d       * S_ + s + 8] = __float2half(x2);
                dst[(size_t)(d + 1) * S_ + s + 8] = __float2half(x3);
            }
        }
    }
#undef AT
#undef BT
}

// ---------------------------------------------------------------------------
// Kernel 2: flash attention. 8 warps x 16 q-rows, 64-key tiles, ldmatrix.x4,
//   exp2-domain softmax (Q pre-scaled by log2e/8), P stays in registers.
// ---------------------------------------------------------------------------
#define FS 36
#define FL_SMEM ((4 * 64 * FS + 2 * 64) * 4)

__global__ __launch_bounds__(256, 2) void flash_attn(
    const float* __restrict__ mask, float* __restrict__ out)
{
    extern __shared__ unsigned fsm[];
    unsigned* KsW = fsm;                  // [2][64 keys][FS]   K: [s][d] f16
    unsigned* VtW = fsm + 2 * 64 * FS;    // [2][64 dims][FS]   V^T: [d][s] f16
    float*    Ms  = (float*)(fsm + 4 * 64 * FS);  // [2][64]
#define KT(bf,r,w) KsW[(bf)*64*FS + (r)*FS + (w)]
#define VT(bf,r,w) VtW[(bf)*64*FS + (r)*FS + (w)]

    const int tid  = threadIdx.x;
    const int lane = tid & 31;
    const int wid  = tid >> 5;
    const int g    = lane >> 2;
    const int t    = lane & 3;
    const int grp  = lane >> 3;
    const int lr   = lane & 7;

    const int bh = blockIdx.y;
    const int b  = bh >> 4, h = bh & 15;
    const __half* Qp  = g_qh + (size_t)bh * S_ * HD_;
    const __half* Kp  = g_kh + (size_t)bh * S_ * HD_;
    const __half* Vtp = g_vt + (size_t)bh * HD_ * S_;
    const float* maskp = mask + b * S_;
    const int q0 = blockIdx.x * 128 + wid * 16;

    // per-lane ldmatrix bases: rows (grp>>1 selects tile pair), cols (grp&1).
    const unsigned kBase = (unsigned)__cvta_generic_to_shared(KsW)
        + (((grp >> 1) * 8 + lr) * FS + (grp & 1) * 4) * 4;
    const unsigned vBase = (unsigned)__cvta_generic_to_shared(VtW)
        + (((grp >> 1) * 8 + lr) * FS + (grp & 1) * 4) * 4;

    auto stage = [&](int kt, int bf) {
        #pragma unroll
        for (int i = 0; i < 2; i++) {
            int idx = tid + i * 256;
            int r = idx >> 3, ch = idx & 7;
            cpa16(&KT(bf, r, ch * 4), &Kp[(size_t)(kt + r) * HD_ + ch * 8]);
            cpa16(&VT(bf, r, ch * 4), &Vtp[(size_t)r * S_ + kt + ch * 8]);
        }
        if (tid < 16) cpa16(&Ms[bf * 64 + tid * 4], &maskp[kt + tid * 4]);
    };

    // Q A-fragments (f16 pairs, pre-scaled by log2e/8), resident.
    unsigned qa[4][4];
    {
        const __half* q0p = Qp + (size_t)(q0 + g) * HD_;
        const __half* q8p = q0p + 8 * HD_;
        #pragma unroll
        for (int dc = 0; dc < 4; dc++) {
            qa[dc][0] = *(const unsigned*)(q0p + dc * 16 + 2 * t);
            qa[dc][1] = *(const unsigned*)(q8p + dc * 16 + 2 * t);
            qa[dc][2] = *(const unsigned*)(q0p + dc * 16 + 2 * t + 8);
            qa[dc][3] = *(const unsigned*)(q8p + dc * 16 + 2 * t + 8);
        }
    }

    float o[8][4] = {};
    float mr0 = -1e30f, mr1 = -1e30f, lr0 = 0.f, lr1 = 0.f;

    stage(0, 0);
    CP_COMMIT;

    for (int it = 0; it < S_ / 64; it++) {
        const int bf = it & 1;
        if (it + 1 < S_ / 64) stage((it + 1) * 64, bf ^ 1);
        CP_COMMIT;
        CP_WAIT1;
        __syncthreads();

        // S = Q @ K^T  (log2 domain)
        float s[8][4] = {};
        {
            const unsigned kb = kBase + bf * (64 * FS * 4);
            #pragma unroll
            for (int dc = 0; dc < 4; dc++) {
                #pragma unroll
                for (int j = 0; j < 4; j++) {   // key pairs (nt = 2j, 2j+1)
                    unsigned r0, r1, r2, r3;
                    ldsm4(r0, r1, r2, r3, kb + (j * 16 * FS + dc * 8) * 4);
                    unsigned f0[2] = { r0, r1 }, f1[2] = { r2, r3 };
                    mma16(s[2 * j],     qa[dc], f0);
                    mma16(s[2 * j + 1], qa[dc], f1);
                }
            }
        }

        // mask (scaled into log2 domain) + row max
        float r0 = -1e30f, r1 = -1e30f;
        #pragma unroll
        for (int nt = 0; nt < 8; nt++) {
            float m0 = Ms[bf * 64 + nt * 8 + 2 * t]     * L2E;
            float m1 = Ms[bf * 64 + nt * 8 + 2 * t + 1] * L2E;
            s[nt][0] += m0; s[nt][1] += m1; s[nt][2] += m0; s[nt][3] += m1;
            r0 = fmaxf(r0, fmaxf(s[nt][0], s[nt][1]));
            r1 = fmaxf(r1, fmaxf(s[nt][2], s[nt][3]));
        }
        r0 = fmaxf(r0, __shfl_xor_sync(0xffffffffu, r0, 1));
        r0 = fmaxf(r0, __shfl_xor_sync(0xffffffffu, r0, 2));
        r1 = fmaxf(r1, __shfl_xor_sync(0xffffffffu, r1, 1));
        r1 = fmaxf(r1, __shfl_xor_sync(0xffffffffu, r1, 2));

        float mn0 = fmaxf(mr0, r0), mn1 = fmaxf(mr1, r1);
        float al0 = exp2f(mr0 - mn0), al1 = exp2f(mr1 - mn1);
        mr0 = mn0; mr1 = mn1;

        // P = exp2(S - m), row sums
        float ps0 = 0.f, ps1 = 0.f;
        #pragma unroll
        for (int nt = 0; nt < 8; nt++) {
            s[nt][0] = exp2f(s[nt][0] - mn0);
            s[nt][1] = exp2f(s[nt][1] - mn0);
            s[nt][2] = exp2f(s[nt][2] - mn1);
            s[nt][3] = exp2f(s[nt][3] - mn1);
            ps0 += s[nt][0] + s[nt][1];
            ps1 += s[nt][2] + s[nt][3];
        }
        ps0 += __shfl_xor_sync(0xffffffffu, ps0, 1);
        ps0 += __shfl_xor_sync(0xffffffffu, ps0, 2);
        ps1 += __shfl_xor_sync(0xffffffffu, ps1, 1);
        ps1 += __shfl_xor_sync(0xffffffffu, ps1, 2);
        lr0 = lr0 * al0 + ps0;
        lr1 = lr1 * al1 + ps1;

        // O = O*alpha + P @ V ; P packed from C-frags into A-frags.
        #pragma unroll
        for (int dt = 0; dt < 8; dt++) {
            o[dt][0] *= al0; o[dt][1] *= al0;
            o[dt][2] *= al1; o[dt][3] *= al1;
        }
        {
            const unsigned vb = vBase + bf * (64 * FS * 4);
            #pragma unroll
            for (int kc = 0; kc < 4; kc++) {
                unsigned a[4] = { h2u(s[2*kc][0],   s[2*kc][1]),
                                  h2u(s[2*kc][2],   s[2*kc][3]),
                                  h2u(s[2*kc+1][0], s[2*kc+1][1]),
                                  h2u(s[2*kc+1][2], s[2*kc+1][3]) };
                #pragma unroll
                for (int j = 0; j < 4; j++) {   // dim pairs (dt = 2j, 2j+1)
                    unsigned r0, r1, r2, r3;
                    ldsm4(r0, r1, r2, r3, vb + (j * 16 * FS + kc * 8) * 4);
                    unsigned f0[2] = { r0, r1 }, f1[2] = { r2, r3 };
                    mma16(o[2 * j],     a, f0);
                    mma16(o[2 * j + 1], a, f1);
                }
            }
        }
        __syncthreads();
    }

    // Normalize and write ctx [B, S, NH*HD] f32.
    const float i0 = 1.0f / lr0, i1 = 1.0f / lr1;
    #pragma unroll
    for (int dt = 0; dt < 8; dt++) {
        size_t base = (size_t)(b * S_ + q0 + g) * H_ + h * HD_ + dt * 8 + 2 * t;
        *(float2*)&out[base] = make_float2(o[dt][0] * i0, o[dt][1] * i0);
        *(float2*)&out[base + 8 * (size_t)H_] =
            make_float2(o[dt][2] * i1, o[dt][3] * i1);
    }
#undef KT
#undef VT
}

// ---------------------------------------------------------------------------
extern "C" void kernel_launch(void* const* d_in, const int* in_sizes, int n_in,
                              void* d_out, int out_size)
{
    const float* hs   = (const float*)d_in[0];
    const float* mask = (const float*)d_in[1];
    const float* Wq   = (const float*)d_in[2];
    const float* bq   = (const float*)d_in[3];
    const float* Wk   = (const float*)d_in[4];
    const float* bk   = (const float*)d_in[5];
    const float* Wv   = (const float*)d_in[6];
    const float* bv   = (const float*)d_in[7];
    const float* qe   = (const float*)d_in[8];
    const float* ke   = (const float*)d_in[9];
    const float* ve   = (const float*)d_in[10];
    const int*   idx  = (const int*)d_in[11];

    cudaFuncSetAttribute(qkv_proj, cudaFuncAttributeMaxDynamicSharedMemorySize,
                         QKV_SMEM);
    cudaFuncSetAttribute(flash_attn, cudaFuncAttributeMaxDynamicSharedMemorySize,
                         FL_SMEM);

    cvt_hs<<<8192, 256>>>(hs);
    cvt_wt<<<dim3(32, 32, 3), dim3(32, 8)>>>(Wq, Wk, Wv);

    dim3 g1(24, 64);
    qkv_proj<<<g1, 256, QKV_SMEM>>>(bq, bk, bv, qe, ke, ve, idx);

    dim3 g2(S_ / 128, B_ * NH_);
    flash_attn<<<g2, 256, FL_SMEM>>>(mask, (float*)d_out);
}

// round 12
// speedup vs baseline: 1.3598x; 1.3598x over previous
#include <cuda_runtime.h>
#include <cuda_fp16.h>
#include <cstdint>
#include <math.h>

#define B_  4
#define S_  2048
#define H_  1024
#define NH_ 16
#define HD_ 64
#define L2E 1.44269504088896f

// f16 scratch.
__device__ __half g_hs[8192 * 1024];          // hidden, f16 [8192][1024]
__device__ __half g_wt[3][1024 * 1024];       // W^T f16 [n][k] for Q,K,V
__device__ __half g_qh[64 * 2048 * 64];       // Q f16 [bh][s][d], scaled log2e/8
__device__ __half g_kh[64 * 2048 * 64];       // K f16 [bh][s][d]
__device__ __half g_vt[64 * 64 * 2048];       // V^T f16 [bh][d][s]

__device__ __forceinline__ void mma16(float* c, const unsigned* a, const unsigned* b) {
    asm volatile(
        "mma.sync.aligned.m16n8k16.row.col.f32.f16.f16.f32 "
        "{%0,%1,%2,%3}, {%4,%5,%6,%7}, {%8,%9}, {%0,%1,%2,%3};\n"
        : "+f"(c[0]), "+f"(c[1]), "+f"(c[2]), "+f"(c[3])
        : "r"(a[0]), "r"(a[1]), "r"(a[2]), "r"(a[3]), "r"(b[0]), "r"(b[1]));
}

__device__ __forceinline__ void cpa16(void* dst, const void* src) {
    unsigned d = (unsigned)__cvta_generic_to_shared(dst);
    asm volatile("cp.async.cg.shared.global [%0], [%1], 16;\n" :: "r"(d), "l"(src));
}
#define CP_COMMIT asm volatile("cp.async.commit_group;\n" ::: "memory")
#define CP_WAIT1  asm volatile("cp.async.wait_group 1;\n" ::: "memory")

__device__ __forceinline__ unsigned h2u(float x, float y) {
    __half2 h = __floats2half2_rn(x, y);
    return *reinterpret_cast<unsigned*>(&h);
}

// ---------------------------------------------------------------------------
// Prep 1: hidden f32 -> f16.
// ---------------------------------------------------------------------------
__global__ __launch_bounds__(256) void cvt_hs(const float* __restrict__ hs) {
    int i = blockIdx.x * 256 + threadIdx.x;
    float4 v = ((const float4*)hs)[i];
    ((uint2*)g_hs)[i] = make_uint2(h2u(v.x, v.y), h2u(v.z, v.w));
}

// ---------------------------------------------------------------------------
// Prep 2: W -> W^T f16 (tiled transpose). grid (32,32,3), block (32,8).
// ---------------------------------------------------------------------------
__global__ __launch_bounds__(256) void cvt_wt(
    const float* __restrict__ Wq, const float* __restrict__ Wk,
    const float* __restrict__ Wv)
{
    __shared__ float t[32][33];
    const float* W = blockIdx.z == 0 ? Wq : (blockIdx.z == 1 ? Wk : Wv);
    __half* wt = g_wt[blockIdx.z];
    int tx = threadIdx.x, ty = threadIdx.y;
    int n0 = blockIdx.x * 32, k0 = blockIdx.y * 32;
    #pragma unroll
    for (int j = 0; j < 4; j++)
        t[ty + 8 * j][tx] = W[(size_t)(k0 + ty + 8 * j) * H_ + n0 + tx];
    __syncthreads();
    #pragma unroll
    for (int j = 0; j < 4; j++)
        wt[(size_t)(n0 + ty + 8 * j) * H_ + k0 + tx] =
            __float2half(t[tx][ty + 8 * j]);
}

// ---------------------------------------------------------------------------
// Kernel 1: fused QKV projection, f16 mma m16n8k16, cp.async double-buffered.
//   BM=128, BN=128, BK=32. 8 warps (4m x 2n), warp tile 32x64.
//   (Round-7 proven version; compiler-scheduled fragment LDS.)
// ---------------------------------------------------------------------------
#define TS 20   // tile row stride in 32-bit words (16 data + 4 pad)
#define QKV_SMEM ((2 * 128 * TS + 2 * 128 * TS) * 4)

__global__ __launch_bounds__(256, 2) void qkv_proj(
    const float* __restrict__ bq, const float* __restrict__ bk,
    const float* __restrict__ bv,
    const float* __restrict__ qe, const float* __restrict__ ke,
    const float* __restrict__ ve,
    const int* __restrict__ indexp)
{
    extern __shared__ unsigned qsm[];
    unsigned* AsW = qsm;                  // [2][128][TS]
    unsigned* BsW = qsm + 2 * 128 * TS;   // [2][128][TS]
#define AT(bf,r,w) AsW[(bf)*128*TS + (r)*TS + (w)]
#define BT(bf,r,w) BsW[(bf)*128*TS + (r)*TS + (w)]

    const int tid  = threadIdx.x;
    const int lane = tid & 31;
    const int wid  = tid >> 5;
    const int g    = lane >> 2;
    const int t    = lane & 3;
    const int wm   = wid & 3;
    const int wn   = wid >> 2;

    const int nb  = blockIdx.x;   // 0..23, 8 per matrix
    const int mb  = blockIdx.y;   // 0..63
    const int sel = nb >> 3;      // 0=Q, 1=K, 2=V

    const __half* wt  = g_wt[sel];
    const float* bias = sel == 0 ? bq : (sel == 1 ? bk : bv);
    const float* emb  = (sel == 0 ? qe : (sel == 1 ? ke : ve)) + indexp[0] * H_;
    const float sc    = sel == 0 ? (0.125f * L2E) : 1.0f;

    const int colm = (nb & 7) * 128;
    const int row0 = mb * 128;

    float acc[2][8][4] = {};

    auto stage = [&](int kt, int bf) {
        #pragma unroll
        for (int i = 0; i < 2; i++) {
            int idx = tid + i * 256;
            int r = idx >> 2, ch = idx & 3;
            cpa16(&AT(bf, r, ch * 4), &g_hs[(size_t)(row0 + r) * H_ + kt + ch * 8]);
            cpa16(&BT(bf, r, ch * 4), &wt[(size_t)(colm + r) * H_ + kt + ch * 8]);
        }
    };

    stage(0, 0);
    CP_COMMIT;

    for (int it = 0; it < H_ / 32; it++) {
        const int bf = it & 1;
        if (it + 1 < H_ / 32) stage((it + 1) * 32, bf ^ 1);
        CP_COMMIT;
        CP_WAIT1;
        __syncthreads();

        #pragma unroll
        for (int kk = 0; kk < 2; kk++) {
            unsigned a[2][4];
            #pragma unroll
            for (int mt = 0; mt < 2; mt++) {
                int r = wm * 32 + mt * 16;
                a[mt][0] = AT(bf, r + g,     kk * 8 + t);
                a[mt][1] = AT(bf, r + g + 8, kk * 8 + t);
                a[mt][2] = AT(bf, r + g,     kk * 8 + t + 4);
                a[mt][3] = AT(bf, r + g + 8, kk * 8 + t + 4);
            }
            #pragma unroll
            for (int nt = 0; nt < 8; nt++) {
                int c = wn * 64 + nt * 8 + g;
                unsigned bb[2] = { BT(bf, c, kk * 8 + t),
                                   BT(bf, c, kk * 8 + t + 4) };
                mma16(acc[0][nt], a[0], bb);
                mma16(acc[1][nt], a[1], bb);
            }
        }
        __syncthreads();
    }

    // Epilogue: +bias+emb, (Q: *log2e/8), f16, scatter.
    #pragma unroll
    for (int nt = 0; nt < 8; nt++) {
        const int cm   = colm + wn * 64 + nt * 8 + 2 * t;
        const float b0 = bias[cm]     + emb[cm];
        const float b1 = bias[cm + 1] + emb[cm + 1];
        const int head = cm >> 6;
        const int d    = cm & 63;
        #pragma unroll
        for (int mt = 0; mt < 2; mt++) {
            int row = row0 + wm * 32 + mt * 16 + g;
            int bt  = row >> 11;
            int s   = row & 2047;
            int bh  = bt * NH_ + head;
            float x0 = (acc[mt][nt][0] + b0) * sc;
            float x1 = (acc[mt][nt][1] + b1) * sc;
            float x2 = (acc[mt][nt][2] + b0) * sc;
            float x3 = (acc[mt][nt][3] + b1) * sc;
            if (sel < 2) {
                __half* dst = (sel ? g_kh : g_qh)
                            + ((size_t)bh * S_ + s) * HD_ + d;
                *(unsigned*)dst             = h2u(x0, x1);
                *(unsigned*)(dst + 8 * HD_) = h2u(x2, x3);
            } else {
                __half* dst = g_vt + (size_t)bh * HD_ * S_;
                dst[(size_t)d       * S_ + s]     = __float2half(x0);
                dst[(size_t)(d + 1) * S_ + s]     = __float2half(x1);
                dst[(size_t)d       * S_ + s + 8] = __float2half(x2);
                dst[(size_t)(d + 1) * S_ + s + 8] = __float2half(x3);
            }
        }
    }
#undef AT
#undef BT
}

// ---------------------------------------------------------------------------
// Kernel 2: flash attention. 8 warps x 16 q-rows, 64-key tiles.
//   3-stage cp.async ring, ONE __syncthreads per tile. exp2-domain softmax.
//   P stays in registers. Compiler-scheduled fragment LDS (no ldmatrix).
// ---------------------------------------------------------------------------
#define FS 36
#define FL_SMEM ((3 * 2 * 64 * FS + 3 * 64) * 4)   // K+V x3 stages + mask x3

__global__ __launch_bounds__(256, 2) void flash_attn(
    const float* __restrict__ mask, float* __restrict__ out)
{
    extern __shared__ unsigned fsm[];
    unsigned* KsW = fsm;                  // [3][64 keys][FS]   K: [s][d] f16
    unsigned* VtW = fsm + 3 * 64 * FS;    // [3][64 dims][FS]   V^T: [d][s] f16
    float*    Ms  = (float*)(fsm + 6 * 64 * FS);  // [3][64]
#define KT(bf,r,w) KsW[(bf)*64*FS + (r)*FS + (w)]
#define VT(bf,r,w) VtW[(bf)*64*FS + (r)*FS + (w)]

    const int tid  = threadIdx.x;
    const int lane = tid & 31;
    const int wid  = tid >> 5;
    const int g    = lane >> 2;
    const int t    = lane & 3;

    const int bh = blockIdx.y;
    const int b  = bh >> 4, h = bh & 15;
    const __half* Qp  = g_qh + (size_t)bh * S_ * HD_;
    const __half* Kp  = g_kh + (size_t)bh * S_ * HD_;
    const __half* Vtp = g_vt + (size_t)bh * HD_ * S_;
    const float* maskp = mask + b * S_;
    const int q0 = blockIdx.x * 128 + wid * 16;

    auto stage = [&](int kt, int bf) {
        #pragma unroll
        for (int i = 0; i < 2; i++) {
            int idx = tid + i * 256;
            int r = idx >> 3, ch = idx & 7;
            cpa16(&KT(bf, r, ch * 4), &Kp[(size_t)(kt + r) * HD_ + ch * 8]);
            cpa16(&VT(bf, r, ch * 4), &Vtp[(size_t)r * S_ + kt + ch * 8]);
        }
        if (tid < 16) cpa16(&Ms[bf * 64 + tid * 4], &maskp[kt + tid * 4]);
    };

    // Q A-fragments (f16 pairs, pre-scaled by log2e/8), resident.
    unsigned qa[4][4];
    {
        const __half* q0p = Qp + (size_t)(q0 + g) * HD_;
        const __half* q8p = q0p + 8 * HD_;
        #pragma unroll
        for (int dc = 0; dc < 4; dc++) {
            qa[dc][0] = *(const unsigned*)(q0p + dc * 16 + 2 * t);
            qa[dc][1] = *(const unsigned*)(q8p + dc * 16 + 2 * t);
            qa[dc][2] = *(const unsigned*)(q0p + dc * 16 + 2 * t + 8);
            qa[dc][3] = *(const unsigned*)(q8p + dc * 16 + 2 * t + 8);
        }
    }

    float o[8][4] = {};
    float mr0 = -1e30f, mr1 = -1e30f, lr0 = 0.f, lr1 = 0.f;

    // Ring prologue: stages 0 and 1 in flight.
    stage(0, 0);
    CP_COMMIT;
    stage(64, 1);
    CP_COMMIT;

    int bf = 0, bs = 2;   // compute buffer, next stage buffer
    for (int it = 0; it < S_ / 64; it++) {
        CP_WAIT1;          // group 'it' complete (one group may stay in flight)
        __syncthreads();   // single barrier per tile; bounds warp skew to <1 iter

        // S = Q @ K^T  (log2 domain)
        float s[8][4] = {};
        #pragma unroll
        for (int dc = 0; dc < 4; dc++) {
            #pragma unroll
            for (int nt = 0; nt < 8; nt++) {
                unsigned bb[2] = { KT(bf, nt * 8 + g, dc * 8 + t),
                                   KT(bf, nt * 8 + g, dc * 8 + t + 4) };
                mma16(s[nt], qa[dc], bb);
            }
        }

        // mask (scaled into log2 domain) + row max
        float r0 = -1e30f, r1 = -1e30f;
        #pragma unroll
        for (int nt = 0; nt < 8; nt++) {
            float m0 = Ms[bf * 64 + nt * 8 + 2 * t]     * L2E;
            float m1 = Ms[bf * 64 + nt * 8 + 2 * t + 1] * L2E;
            s[nt][0] += m0; s[nt][1] += m1; s[nt][2] += m0; s[nt][3] += m1;
            r0 = fmaxf(r0, fmaxf(s[nt][0], s[nt][1]));
            r1 = fmaxf(r1, fmaxf(s[nt][2], s[nt][3]));
        }
        r0 = fmaxf(r0, __shfl_xor_sync(0xffffffffu, r0, 1));
        r0 = fmaxf(r0, __shfl_xor_sync(0xffffffffu, r0, 2));
        r1 = fmaxf(r1, __shfl_xor_sync(0xffffffffu, r1, 1));
        r1 = fmaxf(r1, __shfl_xor_sync(0xffffffffu, r1, 2));

        float mn0 = fmaxf(mr0, r0), mn1 = fmaxf(mr1, r1);
        float al0 = exp2f(mr0 - mn0), al1 = exp2f(mr1 - mn1);
        mr0 = mn0; mr1 = mn1;

        // P = exp2(S - m), row sums
        float ps0 = 0.f, ps1 = 0.f;
        #pragma unroll
        for (int nt = 0; nt < 8; nt++) {
            s[nt][0] = exp2f(s[nt][0] - mn0);
            s[nt][1] = exp2f(s[nt][1] - mn0);
            s[nt][2] = exp2f(s[nt][2] - mn1);
            s[nt][3] = exp2f(s[nt][3] - mn1);
            ps0 += s[nt][0] + s[nt][1];
            ps1 += s[nt][2] + s[nt][3];
        }
        ps0 += __shfl_xor_sync(0xffffffffu, ps0, 1);
        ps0 += __shfl_xor_sync(0xffffffffu, ps0, 2);
        ps1 += __shfl_xor_sync(0xffffffffu, ps1, 1);
        ps1 += __shfl_xor_sync(0xffffffffu, ps1, 2);
        lr0 = lr0 * al0 + ps0;
        lr1 = lr1 * al1 + ps1;

        // O = O*alpha + P @ V ; P packed from C-frags into A-frags.
        #pragma unroll
        for (int dt = 0; dt < 8; dt++) {
            o[dt][0] *= al0; o[dt][1] *= al0;
            o[dt][2] *= al1; o[dt][3] *= al1;
        }
        #pragma unroll
        for (int kc = 0; kc < 4; kc++) {
            unsigned a[4] = { h2u(s[2*kc][0],   s[2*kc][1]),
                              h2u(s[2*kc][2],   s[2*kc][3]),
                              h2u(s[2*kc+1][0], s[2*kc+1][1]),
                              h2u(s[2*kc+1][2], s[2*kc+1][3]) };
            #pragma unroll
            for (int dt = 0; dt < 8; dt++) {
                unsigned bb[2] = { VT(bf, dt * 8 + g, kc * 8 + t),
                                   VT(bf, dt * 8 + g, kc * 8 + t + 4) };
                mma16(o[dt], a, bb);
            }
        }

        // Stage tile it+2 into ring slot bs (its old readers finished at
        // iteration it-1; the barrier above proves all warps are past that).
        if (it + 2 < S_ / 64) stage((it + 2) * 64, bs);
        CP_COMMIT;   // unconditional: empty groups keep wait_group bookkeeping exact

        bf = bf == 2 ? 0 : bf + 1;
        bs = bs == 2 ? 0 : bs + 1;
    }

    // Normalize and write ctx [B, S, NH*HD] f32.
    const float i0 = 1.0f / lr0, i1 = 1.0f / lr1;
    #pragma unroll
    for (int dt = 0; dt < 8; dt++) {
        size_t base = (size_t)(b * S_ + q0 + g) * H_ + h * HD_ + dt * 8 + 2 * t;
        *(float2*)&out[base] = make_float2(o[dt][0] * i0, o[dt][1] * i0);
        *(float2*)&out[base + 8 * (size_t)H_] =
            make_float2(o[dt][2] * i1, o[dt][3] * i1);
    }
#undef KT
#undef VT
}

// ---------------------------------------------------------------------------
extern "C" void kernel_launch(void* const* d_in, const int* in_sizes, int n_in,
                              void* d_out, int out_size)
{
    const float* hs   = (const float*)d_in[0];
    const float* mask = (const float*)d_in[1];
    const float* Wq   = (const float*)d_in[2];
    const float* bq   = (const float*)d_in[3];
    const float* Wk   = (const float*)d_in[4];
    const float* bk   = (const float*)d_in[5];
    const float* Wv   = (const float*)d_in[6];
    const float* bv   = (const float*)d_in[7];
    const float* qe   = (const float*)d_in[8];
    const float* ke   = (const float*)d_in[9];
    const float* ve   = (const float*)d_in[10];
    const int*   idx  = (const int*)d_in[11];

    cudaFuncSetAttribute(qkv_proj, cudaFuncAttributeMaxDynamicSharedMemorySize,
                         QKV_SMEM);
    cudaFuncSetAttribute(flash_attn, cudaFuncAttributeMaxDynamicSharedMemorySize,
                         FL_SMEM);

    cvt_hs<<<8192, 256>>>(hs);
    cvt_wt<<<dim3(32, 32, 3), dim3(32, 8)>>>(Wq, Wk, Wv);

    dim3 g1(24, 64);
    qkv_proj<<<g1, 256, QKV_SMEM>>>(bq, bk, bv, qe, ke, ve, idx);

    dim3 g2(S_ / 128, B_ * NH_);
    flash_attn<<<g2, 256, FL_SMEM>>>(mask, (float*)d_out);
}